// round 5
// baseline (speedup 1.0000x reference)
#include <cuda_runtime.h>
#include <math.h>

typedef unsigned long long u64;

#define NFRAME 300
#define LFRAME 512
#define NLAG   256
#define TSAMP  20000
#define BFDIM  200          // 4 * 50

// ---- shared memory layout (in float words) ----
// sw[c][784]   : windowed frame, circularly extended: sw[c][m] = f_c[m % 512], m in [0,784)
// sws[c][784]  : shift-by-one copy: sws[c][m] = f_c[(m+1) % 512]   (8-word pad before it)
// sacf[2][256] : per-channel relu'd ACF for the normalization / channel-mean epilogue
#define SW0    0
#define SWS0   (2*784 + 8)
#define ACF0   (SWS0 + 2*784)
#define SHMW   (ACF0 + 2*256)

// Packed fp32x2 FMA (Blackwell FFMA2 — only reachable via PTX fma.rn.f32x2)
#define FMA2(acc, a, b) asm("fma.rn.f32x2 %0, %1, %2, %0;" : "+l"(acc) : "l"(a), "l"(b))

// One macro-step: 8 consecutive n values x 8 lags (stride 2) = 64 packed MACs.
// Invariant on entry: V0..V11 hold sb[NN+0 .. NN+23] as (lo,hi) fp32 pairs.
// Loads refill V12..V15 with sb[NN+24 .. NN+31] for the next (rotated) step.
#define STEP(NN, V0,V1,V2,V3,V4,V5,V6,V7,V8,V9,V10,V11,V12,V13,V14,V15)               \
  {                                                                                    \
    ulonglong2 ta0 = *(const ulonglong2 *)(sa + (NN));                                 \
    ulonglong2 ta1 = *(const ulonglong2 *)(sa + (NN) + 4);                             \
    ulonglong2 tb0 = *(const ulonglong2 *)(sb + (NN) + 24);                            \
    ulonglong2 tb1 = *(const ulonglong2 *)(sb + (NN) + 28);                            \
    u64 a0 = ta0.x, a1 = ta0.y, a2 = ta1.x, a3 = ta1.y;                                \
    FMA2(acc0, a0, V0);  FMA2(acc1, a0, V1);  FMA2(acc2, a0, V2);  FMA2(acc3, a0, V3); \
    FMA2(acc4, a0, V4);  FMA2(acc5, a0, V5);  FMA2(acc6, a0, V6);  FMA2(acc7, a0, V7); \
    FMA2(acc0, a1, V1);  FMA2(acc1, a1, V2);  FMA2(acc2, a1, V3);  FMA2(acc3, a1, V4); \
    FMA2(acc4, a1, V5);  FMA2(acc5, a1, V6);  FMA2(acc6, a1, V7);  FMA2(acc7, a1, V8); \
    FMA2(acc0, a2, V2);  FMA2(acc1, a2, V3);  FMA2(acc2, a2, V4);  FMA2(acc3, a2, V5); \
    FMA2(acc4, a2, V6);  FMA2(acc5, a2, V7);  FMA2(acc6, a2, V8);  FMA2(acc7, a2, V9); \
    FMA2(acc0, a3, V3);  FMA2(acc1, a3, V4);  FMA2(acc2, a3, V5);  FMA2(acc3, a3, V6); \
    FMA2(acc4, a3, V7);  FMA2(acc5, a3, V8);  FMA2(acc6, a3, V9);  FMA2(acc7, a3, V10);\
    V12 = tb0.x; V13 = tb0.y; V14 = tb1.x; V15 = tb1.y;                                \
  }

__global__ void __launch_bounds__(64)
acf_kernel(const float* __restrict__ in, float* __restrict__ out)
{
    __shared__ __align__(16) float shm[SHMW];

    const int t   = blockIdx.x;   // frame index 0..299
    const int bf  = blockIdx.y;   // fused (batch, freq) 0..199
    const int tid = threadIdx.x;  // 0..63

    // Exact replica of np.linspace(0, 19488, 300).astype(int64)
    const double delta = (double)(TSAMP - LFRAME) / (double)(NFRAME - 1);
    const int S = (t == NFRAME - 1) ? (TSAMP - LFRAME) : (int)((double)t * delta);

    // -------- load + window + build circular (and shift-by-1) extensions --------
    // input layout: nervegram[b, f, time, c] -> channels adjacent => one float2 per time
    const float2* __restrict__ src = (const float2*)in + (size_t)bf * TSAMP + S;
    #pragma unroll
    for (int it = 0; it < 8; ++it) {
        const int n = tid + 64 * it;                       // 0..511
        const float2 v = src[n];
        const float wn = 0.5f - 0.5f * cosf((float)n * 0.012271846303085130f); // 2*pi/512
        const float f0 = wn * v.x;
        const float f1 = wn * v.y;
        shm[SW0 + n]        = f0;
        shm[SW0 + 784 + n]  = f1;
        const int m = (n + 511) & 511;                     // n-1 mod 512
        shm[SWS0 + m]       = f0;
        shm[SWS0 + 784 + m] = f1;
        if (n < 272)           { shm[SW0  + n + 512] = f0;  shm[SW0  + 784 + n + 512] = f1; }
        if (n >= 1 && n < 273) { shm[SWS0 + n + 511] = f0;  shm[SWS0 + 784 + n + 511] = f1; }
    }
    __syncthreads();

    // -------- per-thread lag assignment --------
    // warp = channel; lane -> (parity p, group g); lags = 16g + p + {0,2,...,14}
    const int c    = tid >> 5;
    const int lane = tid & 31;
    const int p    = lane & 1;
    const int g    = lane >> 1;
    const int K    = 16 * g + p;

    const float* sa = shm + SW0 + 784 * c;                               // f_c[n]
    const float* sb = (p ? (shm + SWS0 + 784 * c) : sa) + 16 * g;        // f_c[(n + K + .) mod 512]

    u64 acc0 = 0, acc1 = 0, acc2 = 0, acc3 = 0, acc4 = 0, acc5 = 0, acc6 = 0, acc7 = 0;
    u64 U0,U1,U2,U3,U4,U5,U6,U7,U8,U9,U10,U11,U12,U13,U14,U15;

    // prologue: U0..U11 = sb[0..23]
    {
        ulonglong2 q;
        q = *(const ulonglong2*)(sb +  0); U0  = q.x; U1  = q.y;
        q = *(const ulonglong2*)(sb +  4); U2  = q.x; U3  = q.y;
        q = *(const ulonglong2*)(sb +  8); U4  = q.x; U5  = q.y;
        q = *(const ulonglong2*)(sb + 12); U6  = q.x; U7  = q.y;
        q = *(const ulonglong2*)(sb + 16); U8  = q.x; U9  = q.y;
        q = *(const ulonglong2*)(sb + 20); U10 = q.x; U11 = q.y;
    }

    // main loop: 64 macro-steps of 8 n-values, window registers rotate with period 4
    for (int n8 = 0; n8 < 512; n8 += 32) {
        STEP(n8,      U0,U1,U2,U3,U4,U5,U6,U7,U8,U9,U10,U11,U12,U13,U14,U15);
        STEP(n8 +  8, U4,U5,U6,U7,U8,U9,U10,U11,U12,U13,U14,U15,U0,U1,U2,U3);
        STEP(n8 + 16, U8,U9,U10,U11,U12,U13,U14,U15,U0,U1,U2,U3,U4,U5,U6,U7);
        STEP(n8 + 24, U12,U13,U14,U15,U0,U1,U2,U3,U4,U5,U6,U7,U8,U9,U10,U11);
    }

    // -------- epilogue: fold packed halves, relu, stage per-channel ACF --------
    float* sacf = shm + ACF0;
    {
        float lo, hi;
        asm("mov.b64 {%0,%1}, %2;" : "=f"(lo), "=f"(hi) : "l"(acc0));
        sacf[c * NLAG + K +  0] = fmaxf(lo + hi, 0.f);
        asm("mov.b64 {%0,%1}, %2;" : "=f"(lo), "=f"(hi) : "l"(acc1));
        sacf[c * NLAG + K +  2] = fmaxf(lo + hi, 0.f);
        asm("mov.b64 {%0,%1}, %2;" : "=f"(lo), "=f"(hi) : "l"(acc2));
        sacf[c * NLAG + K +  4] = fmaxf(lo + hi, 0.f);
        asm("mov.b64 {%0,%1}, %2;" : "=f"(lo), "=f"(hi) : "l"(acc3));
        sacf[c * NLAG + K +  6] = fmaxf(lo + hi, 0.f);
        asm("mov.b64 {%0,%1}, %2;" : "=f"(lo), "=f"(hi) : "l"(acc4));
        sacf[c * NLAG + K +  8] = fmaxf(lo + hi, 0.f);
        asm("mov.b64 {%0,%1}, %2;" : "=f"(lo), "=f"(hi) : "l"(acc5));
        sacf[c * NLAG + K + 10] = fmaxf(lo + hi, 0.f);
        asm("mov.b64 {%0,%1}, %2;" : "=f"(lo), "=f"(hi) : "l"(acc6));
        sacf[c * NLAG + K + 12] = fmaxf(lo + hi, 0.f);
        asm("mov.b64 {%0,%1}, %2;" : "=f"(lo), "=f"(hi) : "l"(acc7));
        sacf[c * NLAG + K + 14] = fmaxf(lo + hi, 0.f);
    }
    __syncthreads();

    // -------- normalize per channel, mean over channels, store --------
    const float n0 = sacf[0];
    const float n1 = sacf[NLAG];
    const float i0 = (n0 == 0.f) ? 1.f : rsqrtf(n0);
    const float i1 = (n1 == 0.f) ? 1.f : rsqrtf(n1);
    float* __restrict__ op = out + ((size_t)bf * NFRAME + t) * NLAG;
    #pragma unroll
    for (int k = tid; k < NLAG; k += 64) {
        op[k] = 0.5f * (sacf[k] * i0 + sacf[NLAG + k] * i1);
    }
}

extern "C" void kernel_launch(void* const* d_in, const int* in_sizes, int n_in,
                              void* d_out, int out_size)
{
    (void)in_sizes; (void)n_in; (void)out_size;
    const float* in = (const float*)d_in[0];
    float* out = (float*)d_out;
    dim3 grid(NFRAME, BFDIM);
    acf_kernel<<<grid, 64>>>(in, out);
}